// round 15
// baseline (speedup 1.0000x reference)
#include <cuda_runtime.h>
#include <cuda_fp16.h>
#include <cstdint>

#define NN  100000
#define EP  1600000
#define ET  3200000
#define FIN 128
#define FH  64
#define FO  32
#define NB  ((NN + 255) / 256)   // 391 scan blocks

// ---------------- scratch (static device globals; no allocation) ------------
__device__ int    g_deg[NN];               // self-cleaning: scanC re-zeros
__device__ int    g_bsum[512];
__device__ int    g_rowptr[NN + 1];
__device__ int    g_cursor[NN];
__device__ uint2  g_edge[EP];              // {src, __float_as_uint(dinv[src])}
__device__ float  g_dinv[NN];
__device__ __half g_xw[(size_t)NN * FH];   // layer1 linear out (fp16 storage)
__device__ __half g_hw[(size_t)NN * FO];   // layer2 linear out (fp16 storage)
__device__ __half g_z [(size_t)NN * FO];   // layer2 embedding (fp16 storage)

__device__ __forceinline__ int edge_at(const void* p, int is64, size_t idx) {
    if (is64) return (int)((const long long*)p)[idx];
    return ((const int*)p)[idx];
}

// unpack uint2 (4 halves) -> 4 floats
__device__ __forceinline__ float4 h4_to_f4(uint2 u) {
    float2 a = __half22float2(*(__half2*)&u.x);
    float2 b = __half22float2(*(__half2*)&u.y);
    return make_float4(a.x, a.y, b.x, b.y);
}

// per-warp dtype probe: odd 32-bit words are int64 high words (all 0) for i64,
// ~random node ids for i32. Call with ALL lanes active (kernel entry).
__device__ __forceinline__ int probe_is64(const int* p) {
    int lane = threadIdx.x & 31;
    unsigned m = __ballot_sync(0xffffffffu, p[2 * lane + 1] != 0);
    return m == 0;
}

// ---------------- degree histogram (2 edges / thread) ------------------------
__global__ void k_hist(const void* __restrict__ eidx) {
    int is64 = probe_is64((const int*)eidx);
    int i = blockIdx.x * blockDim.x + threadIdx.x;
    if (i * 2 >= EP) return;
    int c0, c1;
    if (is64) {
        longlong2 v = ((const longlong2*)((const long long*)eidx + EP))[i];
        c0 = (int)v.x; c1 = (int)v.y;
    } else {
        int2 v = ((const int2*)((const int*)eidx + EP))[i];
        c0 = v.x; c1 = v.y;
    }
    atomicAdd(&g_deg[c0], 1);
    atomicAdd(&g_deg[c1], 1);
}

// ---------------- scan phase A: per-block sums -------------------------------
__global__ __launch_bounds__(256) void k_scanA() {
    int i = blockIdx.x * 256 + threadIdx.x;
    int lane = threadIdx.x & 31, wid = threadIdx.x >> 5;
    __shared__ int sw[8];
    int v = (i < NN) ? g_deg[i] : 0;
    #pragma unroll
    for (int o = 16; o; o >>= 1) v += __shfl_xor_sync(0xffffffffu, v, o);
    if (lane == 0) sw[wid] = v;
    __syncthreads();
    if (threadIdx.x == 0) {
        int t = 0;
        #pragma unroll
        for (int j = 0; j < 8; j++) t += sw[j];
        g_bsum[blockIdx.x] = t;
    }
}

// ---------------- scan phase C (B fused): offsets + dinv + deg self-clean ----
__global__ __launch_bounds__(256) void k_scanC() {
    __shared__ int sred[8];
    __shared__ int sw[8];
    __shared__ int s_total;
    int tid = threadIdx.x, lane = tid & 31, wid = tid >> 5;
    int part = 0;
    for (int t = tid; t < blockIdx.x; t += 256) part += g_bsum[t];
    #pragma unroll
    for (int o = 16; o; o >>= 1) part += __shfl_xor_sync(0xffffffffu, part, o);
    if (lane == 0) sred[wid] = part;
    __syncthreads();
    int off = sred[0] + sred[1] + sred[2] + sred[3]
            + sred[4] + sred[5] + sred[6] + sred[7];
    int i = blockIdx.x * 256 + tid;
    int v = (i < NN) ? g_deg[i] : 0;
    int incl = v;
    #pragma unroll
    for (int o = 1; o < 32; o <<= 1) {
        int n = __shfl_up_sync(0xffffffffu, incl, o);
        if (lane >= o) incl += n;
    }
    if (lane == 31) sw[wid] = incl;
    __syncthreads();
    if (tid == 0) {
        int run = 0;
        #pragma unroll
        for (int j = 0; j < 8; j++) { int x = sw[j]; sw[j] = run; run += x; }
        s_total = run;
    }
    __syncthreads();
    int excl = off + sw[wid] + incl - v;
    if (i < NN) {
        g_rowptr[i] = excl;
        g_cursor[i] = excl;
        g_dinv[i]   = rsqrtf((float)(v + 1));
        g_deg[i]    = 0;
    }
    if (blockIdx.x == NB - 1 && tid == 0) g_rowptr[NN] = off + s_total;
}

// ---------------- CSR scatter: pack {src, dinv[src]} ------------------------
__global__ void k_scatter(const void* __restrict__ eidx) {
    int is64 = probe_is64((const int*)eidx);
    int i = blockIdx.x * blockDim.x + threadIdx.x;
    if (i * 2 >= EP) return;
    int r0, r1, c0, c1;
    if (is64) {
        const long long* e64 = (const long long*)eidx;
        longlong2 vr = ((const longlong2*)e64)[i];
        longlong2 vc = ((const longlong2*)(e64 + EP))[i];
        r0 = (int)vr.x; r1 = (int)vr.y;
        c0 = (int)vc.x; c1 = (int)vc.y;
    } else {
        const int* e32 = (const int*)eidx;
        int2 vr = ((const int2*)e32)[i];
        int2 vc = ((const int2*)(e32 + EP))[i];
        r0 = vr.x; r1 = vr.y;
        c0 = vc.x; c1 = vc.y;
    }
    float d0 = g_dinv[r0], d1 = g_dinv[r1];
    int p0 = atomicAdd(&g_cursor[c0], 1);
    g_edge[p0] = make_uint2((unsigned)r0, __float_as_uint(d0));
    int p1 = atomicAdd(&g_cursor[c1], 1);
    g_edge[p1] = make_uint2((unsigned)r1, __float_as_uint(d1));
}

// ---------------- GEMM1: 8 rows x 8 cols per thread, fp16 output -------------
__global__ __launch_bounds__(256) void k_gemm1(const float* __restrict__ x,
                                               const float* __restrict__ W) {
    __shared__ float Ws[FIN * FH];                // 32 KB
    int tx = threadIdx.x, ty = threadIdx.y;       // (8, 32)
    int tid = ty * 8 + tx;
    {
        const float4* W4 = (const float4*)W;
        float4* Ws4 = (float4*)Ws;
        for (int i = tid; i < FIN * FH / 4; i += 256) Ws4[i] = W4[i];
    }
    __syncthreads();
    int rbase = blockIdx.x * 256 + ty;            // rows: rbase + 32*i, i<8
    int cb = tx * 8;
    const float4* xp[8];
    bool vr[8];
    #pragma unroll
    for (int i = 0; i < 8; i++) {
        int r = rbase + i * 32;
        vr[i] = r < NN;
        xp[i] = (const float4*)(x + (size_t)(vr[i] ? r : 0) * FIN);
    }
    float acc[8][8];
    #pragma unroll
    for (int i = 0; i < 8; i++)
        #pragma unroll
        for (int j = 0; j < 8; j++) acc[i][j] = 0.f;
    for (int k4 = 0; k4 < FIN / 4; k4++) {
        float4 xv[8];
        #pragma unroll
        for (int i = 0; i < 8; i++) xv[i] = xp[i][k4];
        const float* w = &Ws[(k4 * 4) * FH + cb];
        #pragma unroll
        for (int kk = 0; kk < 4; kk++) {
            const float* wk = w + kk * FH;
            #pragma unroll
            for (int j = 0; j < 8; j++) {
                float wv = wk[j];
                #pragma unroll
                for (int i = 0; i < 8; i++)
                    acc[i][j] = fmaf(((const float*)&xv[i])[kk], wv, acc[i][j]);
            }
        }
    }
    #pragma unroll
    for (int i = 0; i < 8; i++) {
        if (vr[i]) {
            uint4 st;
            __half2 p0 = __floats2half2_rn(acc[i][0], acc[i][1]);
            __half2 p1 = __floats2half2_rn(acc[i][2], acc[i][3]);
            __half2 p2 = __floats2half2_rn(acc[i][4], acc[i][5]);
            __half2 p3 = __floats2half2_rn(acc[i][6], acc[i][7]);
            st.x = *(unsigned*)&p0; st.y = *(unsigned*)&p1;
            st.z = *(unsigned*)&p2; st.w = *(unsigned*)&p3;
            *(uint4*)(g_xw + (size_t)(rbase + i * 32) * FH + cb) = st;
        }
    }
}

// ---------------- agg1 fused with GEMM2: predicated full-width steps ---------
__global__ __launch_bounds__(256) void k_agg1f(const float* __restrict__ b1,
                                               const float* __restrict__ W2) {
    __shared__ float Ws[FH * FO];                 // 8 KB
    int tid = threadIdx.x;
    {
        const float4* W4 = (const float4*)W2;
        float4* Ws4 = (float4*)Ws;
        for (int i = tid; i < FH * FO / 4; i += 256) Ws4[i] = W4[i];
    }
    __syncthreads();
    int w = (blockIdx.x * 256 + tid) >> 5;
    if (w >= NN) return;
    int lane = tid & 31;
    int half_ = lane >> 4, q = lane & 15;         // q: 8B chunk of 128B row
    float dw = g_dinv[w];
    float4 acc = make_float4(0, 0, 0, 0);
    if (half_ == 0) {                             // self loop on half 0
        float4 sv = h4_to_f4(((const uint2*)(g_xw + (size_t)w * FH))[q]);
        acc.x = sv.x * dw; acc.y = sv.y * dw; acc.z = sv.z * dw; acc.w = sv.w * dw;
    }
    int s = g_rowptr[w], e = g_rowptr[w + 1];
    // single predicated loop: every iteration runs at full MLP-8 per lane
    for (int p = s; p < e; p += 16) {
        int  idx[8];
        uint2 r[8];
        #pragma unroll
        for (int t = 0; t < 8; t++) {
            int i0 = p + 2 * t + half_;
            idx[t] = (i0 < e) ? i0 : (e - 1);      // e-1 >= s inside loop
            r[t] = g_edge[idx[t]];
        }
        uint2 u[8];
        #pragma unroll
        for (int t = 0; t < 8; t++)
            u[t] = ((const uint2*)(g_xw + (size_t)r[t].x * FH))[q];
        #pragma unroll
        for (int t = 0; t < 8; t++) {
            int i0 = p + 2 * t + half_;
            float d = (i0 < e) ? __uint_as_float(r[t].y) : 0.f;
            float4 f = h4_to_f4(u[t]);
            acc.x = fmaf(f.x, d, acc.x); acc.y = fmaf(f.y, d, acc.y);
            acc.z = fmaf(f.z, d, acc.z); acc.w = fmaf(f.w, d, acc.w);
        }
    }
    acc.x += __shfl_xor_sync(0xffffffffu, acc.x, 16);
    acc.y += __shfl_xor_sync(0xffffffffu, acc.y, 16);
    acc.z += __shfl_xor_sync(0xffffffffu, acc.z, 16);
    acc.w += __shfl_xor_sync(0xffffffffu, acc.w, 16);
    float4 bias = ((const float4*)b1)[q];
    float4 h;
    h.x = fmaxf(fmaf(acc.x, dw, bias.x), 0.f);
    h.y = fmaxf(fmaf(acc.y, dw, bias.y), 0.f);
    h.z = fmaxf(fmaf(acc.z, dw, bias.z), 0.f);
    h.w = fmaxf(fmaf(acc.w, dw, bias.w), 0.f);
    float o = 0.f;
    #pragma unroll
    for (int f4 = 0; f4 < 16; f4++) {
        float h0 = __shfl_sync(0xffffffffu, h.x, f4);
        float h1 = __shfl_sync(0xffffffffu, h.y, f4);
        float h2 = __shfl_sync(0xffffffffu, h.z, f4);
        float h3 = __shfl_sync(0xffffffffu, h.w, f4);
        o = fmaf(h0, Ws[(f4 * 4 + 0) * FO + lane], o);
        o = fmaf(h1, Ws[(f4 * 4 + 1) * FO + lane], o);
        o = fmaf(h2, Ws[(f4 * 4 + 2) * FO + lane], o);
        o = fmaf(h3, Ws[(f4 * 4 + 3) * FO + lane], o);
    }
    g_hw[(size_t)w * FO + lane] = __float2half_rn(o);
}

// ---------------- agg2: predicated full-width steps; z fp16 ------------------
__global__ __launch_bounds__(256) void k_agg2(const float* __restrict__ b) {
    int w = (blockIdx.x * 256 + threadIdx.x) >> 5;
    if (w >= NN) return;
    int lane = threadIdx.x & 31;
    int g = lane >> 3, l8 = lane & 7;             // l8: 8B chunk of 64B row
    float dw = g_dinv[w];
    float4 acc = make_float4(0, 0, 0, 0);
    if (g == 0) {
        float4 sv = h4_to_f4(((const uint2*)(g_hw + (size_t)w * FO))[l8]);
        acc.x = sv.x * dw; acc.y = sv.y * dw; acc.z = sv.z * dw; acc.w = sv.w * dw;
    }
    int s = g_rowptr[w], e = g_rowptr[w + 1];
    for (int p = s; p < e; p += 8) {              // 2 slots per group of 4
        int i0 = p + g,      j0 = (i0 < e) ? i0 : (e - 1);
        int i1 = p + 4 + g,  j1 = (i1 < e) ? i1 : (e - 1);
        uint2 r0 = g_edge[j0];
        uint2 r1 = g_edge[j1];
        float4 u0 = h4_to_f4(((const uint2*)(g_hw + (size_t)r0.x * FO))[l8]);
        float4 u1 = h4_to_f4(((const uint2*)(g_hw + (size_t)r1.x * FO))[l8]);
        float d0 = (i0 < e) ? __uint_as_float(r0.y) : 0.f;
        float d1 = (i1 < e) ? __uint_as_float(r1.y) : 0.f;
        acc.x = fmaf(u0.x, d0, acc.x); acc.y = fmaf(u0.y, d0, acc.y);
        acc.z = fmaf(u0.z, d0, acc.z); acc.w = fmaf(u0.w, d0, acc.w);
        acc.x = fmaf(u1.x, d1, acc.x); acc.y = fmaf(u1.y, d1, acc.y);
        acc.z = fmaf(u1.z, d1, acc.z); acc.w = fmaf(u1.w, d1, acc.w);
    }
    #pragma unroll
    for (int o = 8; o <= 16; o <<= 1) {
        acc.x += __shfl_xor_sync(0xffffffffu, acc.x, o);
        acc.y += __shfl_xor_sync(0xffffffffu, acc.y, o);
        acc.z += __shfl_xor_sync(0xffffffffu, acc.z, o);
        acc.w += __shfl_xor_sync(0xffffffffu, acc.w, o);
    }
    if (g == 0) {
        float4 bias = ((const float4*)b)[l8];
        __half2 z0 = __floats2half2_rn(fmaf(acc.x, dw, bias.x),
                                       fmaf(acc.y, dw, bias.y));
        __half2 z1 = __floats2half2_rn(fmaf(acc.z, dw, bias.z),
                                       fmaf(acc.w, dw, bias.w));
        uint2 st;
        st.x = *(unsigned*)&z0;
        st.y = *(unsigned*)&z1;
        ((uint2*)(g_z + (size_t)w * FO))[l8] = st;   // 8B per lane, 64B row
    }
}

// ---------------- decode: 32 edges/warp, fp16 z gathers ----------------------
__global__ __launch_bounds__(256) void k_decode(const void* __restrict__ pos,
                                                const void* __restrict__ neg,
                                                float* __restrict__ out) {
    int is64 = probe_is64((const int*)pos);
    int warp = (blockIdx.x * 256 + threadIdx.x) >> 5;
    int lane = threadIdx.x & 31;
    int sub = lane >> 3, l8 = lane & 7;
    size_t base = (size_t)warp * 32 + sub * 8;      // EP%8==0: one-sided
    const void* buf; size_t off;
    if (base < EP) { buf = pos; off = base; }
    else           { buf = neg; off = base - EP; }
    int a[8], c[8];
    if (!is64) {
        const int* e32 = (const int*)buf;
        int4 a0 = *(const int4*)(e32 + off);
        int4 a1 = *(const int4*)(e32 + off + 4);
        int4 c0 = *(const int4*)(e32 + EP + off);
        int4 c1 = *(const int4*)(e32 + EP + off + 4);
        a[0] = a0.x; a[1] = a0.y; a[2] = a0.z; a[3] = a0.w;
        a[4] = a1.x; a[5] = a1.y; a[6] = a1.z; a[7] = a1.w;
        c[0] = c0.x; c[1] = c0.y; c[2] = c0.z; c[3] = c0.w;
        c[4] = c1.x; c[5] = c1.y; c[6] = c1.z; c[7] = c1.w;
    } else {
        const long long* e64 = (const long long*)buf;
        #pragma unroll
        for (int t = 0; t < 4; t++) {
            longlong2 pa = *(const longlong2*)(e64 + off + 2 * t);
            longlong2 pc = *(const longlong2*)(e64 + EP + off + 2 * t);
            a[2 * t] = (int)pa.x; a[2 * t + 1] = (int)pa.y;
            c[2 * t] = (int)pc.x; c[2 * t + 1] = (int)pc.y;
        }
    }
    uint2 ua[8], ub[8];
    #pragma unroll
    for (int t = 0; t < 8; t++) {
        ua[t] = ((const uint2*)(g_z + (size_t)a[t] * FO))[l8];
        ub[t] = ((const uint2*)(g_z + (size_t)c[t] * FO))[l8];
    }
    float v[8];
    #pragma unroll
    for (int t = 0; t < 8; t++) {
        float4 fa = h4_to_f4(ua[t]);
        float4 fb = h4_to_f4(ub[t]);
        v[t] = fa.x * fb.x + fa.y * fb.y + fa.z * fb.z + fa.w * fb.w;
    }
    #pragma unroll
    for (int o = 4; o; o >>= 1) {
        #pragma unroll
        for (int t = 0; t < 8; t++) v[t] += __shfl_xor_sync(0xffffffffu, v[t], o);
    }
    if (l8 == 0) {
        ((float4*)out)[(base >> 2)]     = make_float4(v[0], v[1], v[2], v[3]);
        ((float4*)out)[(base >> 2) + 1] = make_float4(v[4], v[5], v[6], v[7]);
    }
}

// edge_index echoed as floats (2 elems / thread) ------------------------------
__global__ void k_tail(const void* __restrict__ pos,
                       const void* __restrict__ neg,
                       float* __restrict__ out, int count) {
    int is64 = probe_is64((const int*)pos);
    int i = (blockIdx.x * blockDim.x + threadIdx.x) * 2;
    if (i >= count) return;
    int r = i / ET, c = i % ET;                    // ET%2==0: pair same row
    int v0, v1;
    const void* buf = (c < EP) ? pos : neg;
    size_t off = (size_t)r * EP + ((c < EP) ? c : c - EP);
    if (c + 1 == EP || c + 1 == ET) {              // straddle: scalar
        v0 = edge_at(buf, is64, off);
        v1 = (c + 1 < ET) ? edge_at(neg, is64, (size_t)r * EP) :
             ((r == 0) ? edge_at(pos, is64, EP) : 0);
        out[ET + i] = (float)v0;
        if (i + 1 < count) out[ET + i + 1] = (float)v1;
        return;
    }
    if (is64) {
        longlong2 p2 = ((const longlong2*)((const long long*)buf))[off / 2];
        v0 = (int)p2.x; v1 = (int)p2.y;
    } else {
        int2 p2 = ((const int2*)((const int*)buf))[off / 2];
        v0 = p2.x; v1 = p2.y;
    }
    ((float2*)(out + ET))[i / 2] = make_float2((float)v0, (float)v1);
}

// ---------------- launcher ---------------------------------------------------
extern "C" void kernel_launch(void* const* d_in, const int* in_sizes, int n_in,
                              void* d_out, int out_size) {
    static cudaStream_t s2 = 0;
    static cudaEvent_t evFork = 0, evJoin = 0, evTail = 0;
    if (!s2) {
        cudaStreamCreateWithFlags(&s2, cudaStreamNonBlocking);
        cudaEventCreateWithFlags(&evFork, cudaEventDisableTiming);
        cudaEventCreateWithFlags(&evJoin, cudaEventDisableTiming);
        cudaEventCreateWithFlags(&evTail, cudaEventDisableTiming);
    }

    const float *x = 0, *W1 = 0, *b1 = 0, *W2 = 0, *b2 = 0;
    const void *pos = 0, *neg = 0;
    for (int i = 0; i < n_in; i++) {
        switch (in_sizes[i]) {
            case NN * FIN:  x  = (const float*)d_in[i]; break;
            case FIN * FH:  W1 = (const float*)d_in[i]; break;
            case FH:        b1 = (const float*)d_in[i]; break;
            case FH * FO:   W2 = (const float*)d_in[i]; break;
            case FO:        b2 = (const float*)d_in[i]; break;
            case 2 * EP:
                if (!pos) pos = d_in[i];
                else      neg = d_in[i];
                break;
            default: break;
        }
    }
    float* out = (float*)d_out;

    // fork: GEMM1 + edge echo (independent of graph preprocessing) on s2
    cudaEventRecord(evFork, 0);
    cudaStreamWaitEvent(s2, evFork, 0);
    k_gemm1<<<(NN + 255) / 256, dim3(8, 32), 0, s2>>>(x, W1);
    cudaEventRecord(evJoin, s2);
    int cnt = 0;
    if (out_size > ET) {
        cnt = out_size - ET;
        if (cnt > 2 * ET) cnt = 2 * ET;
        k_tail<<<((cnt + 1) / 2 + 255) / 256, 256, 0, s2>>>(pos, neg, out, cnt);
        cudaEventRecord(evTail, s2);
    }

    // preprocessing chain on main stream (deg pre-zeroed: self-cleaning)
    k_hist   <<<(EP / 2 + 255) / 256, 256>>>(pos);
    k_scanA  <<<NB, 256>>>();
    k_scanC  <<<NB, 256>>>();
    k_scatter<<<(EP / 2 + 255) / 256, 256>>>(pos);

    // join gemm1, then fused layer pipeline (flat grids)
    cudaStreamWaitEvent(0, evJoin, 0);
    k_agg1f<<<(NN * 32 + 255) / 256, 256>>>(b1, W2);
    k_agg2 <<<(NN * 32 + 255) / 256, 256>>>(b2);

    // decode writes out[0..ET), tail writes out[ET..): disjoint — join after
    k_decode<<<(ET / 32) * 32 / 256, 256>>>(pos, neg, out);
    if (cnt) cudaStreamWaitEvent(0, evTail, 0);
}

// round 16
// speedup vs baseline: 1.5215x; 1.5215x over previous
#include <cuda_runtime.h>
#include <cuda_fp16.h>
#include <cstdint>

#define NN  100000
#define EP  1600000
#define ET  3200000
#define FIN 128
#define FH  64
#define FO  32
#define NB  ((NN + 255) / 256)   // 391 scan blocks

// ---------------- scratch (static device globals; no allocation) ------------
__device__ int    g_deg[NN];               // self-cleaning: scanC re-zeros
__device__ int    g_bsum[512];
__device__ int    g_rowptr[NN + 1];
__device__ int    g_cursor[NN];
__device__ uint2  g_edge[EP];              // {src, __float_as_uint(dinv[src])}
__device__ float  g_dinv[NN];
__device__ __half g_xw[(size_t)NN * FH];   // layer1 linear out (fp16 storage)
__device__ __half g_hw[(size_t)NN * FO];   // layer2 linear out (fp16 storage)
__device__ __half g_z [(size_t)NN * FO];   // layer2 embedding (fp16 storage)

__device__ __forceinline__ int edge_at(const void* p, int is64, size_t idx) {
    if (is64) return (int)((const long long*)p)[idx];
    return ((const int*)p)[idx];
}

// unpack uint2 (4 halves) -> 4 floats
__device__ __forceinline__ float4 h4_to_f4(uint2 u) {
    float2 a = __half22float2(*(__half2*)&u.x);
    float2 b = __half22float2(*(__half2*)&u.y);
    return make_float4(a.x, a.y, b.x, b.y);
}

// per-warp dtype probe: odd 32-bit words are int64 high words (all 0) for i64,
// ~random node ids for i32. Call with ALL lanes active (kernel entry).
__device__ __forceinline__ int probe_is64(const int* p) {
    int lane = threadIdx.x & 31;
    unsigned m = __ballot_sync(0xffffffffu, p[2 * lane + 1] != 0);
    return m == 0;
}

// ---------------- degree histogram (2 edges / thread) ------------------------
__global__ void k_hist(const void* __restrict__ eidx) {
    int is64 = probe_is64((const int*)eidx);
    int i = blockIdx.x * blockDim.x + threadIdx.x;
    if (i * 2 >= EP) return;
    int c0, c1;
    if (is64) {
        longlong2 v = ((const longlong2*)((const long long*)eidx + EP))[i];
        c0 = (int)v.x; c1 = (int)v.y;
    } else {
        int2 v = ((const int2*)((const int*)eidx + EP))[i];
        c0 = v.x; c1 = v.y;
    }
    atomicAdd(&g_deg[c0], 1);
    atomicAdd(&g_deg[c1], 1);
}

// ---------------- scan phase A: per-block sums -------------------------------
__global__ __launch_bounds__(256) void k_scanA() {
    int i = blockIdx.x * 256 + threadIdx.x;
    int lane = threadIdx.x & 31, wid = threadIdx.x >> 5;
    __shared__ int sw[8];
    int v = (i < NN) ? g_deg[i] : 0;
    #pragma unroll
    for (int o = 16; o; o >>= 1) v += __shfl_xor_sync(0xffffffffu, v, o);
    if (lane == 0) sw[wid] = v;
    __syncthreads();
    if (threadIdx.x == 0) {
        int t = 0;
        #pragma unroll
        for (int j = 0; j < 8; j++) t += sw[j];
        g_bsum[blockIdx.x] = t;
    }
}

// ---------------- scan phase C (B fused): offsets + dinv + deg self-clean ----
__global__ __launch_bounds__(256) void k_scanC() {
    __shared__ int sred[8];
    __shared__ int sw[8];
    __shared__ int s_total;
    int tid = threadIdx.x, lane = tid & 31, wid = tid >> 5;
    int part = 0;
    for (int t = tid; t < blockIdx.x; t += 256) part += g_bsum[t];
    #pragma unroll
    for (int o = 16; o; o >>= 1) part += __shfl_xor_sync(0xffffffffu, part, o);
    if (lane == 0) sred[wid] = part;
    __syncthreads();
    int off = sred[0] + sred[1] + sred[2] + sred[3]
            + sred[4] + sred[5] + sred[6] + sred[7];
    int i = blockIdx.x * 256 + tid;
    int v = (i < NN) ? g_deg[i] : 0;
    int incl = v;
    #pragma unroll
    for (int o = 1; o < 32; o <<= 1) {
        int n = __shfl_up_sync(0xffffffffu, incl, o);
        if (lane >= o) incl += n;
    }
    if (lane == 31) sw[wid] = incl;
    __syncthreads();
    if (tid == 0) {
        int run = 0;
        #pragma unroll
        for (int j = 0; j < 8; j++) { int x = sw[j]; sw[j] = run; run += x; }
        s_total = run;
    }
    __syncthreads();
    int excl = off + sw[wid] + incl - v;
    if (i < NN) {
        g_rowptr[i] = excl;
        g_cursor[i] = excl;
        g_dinv[i]   = rsqrtf((float)(v + 1));
        g_deg[i]    = 0;
    }
    if (blockIdx.x == NB - 1 && tid == 0) g_rowptr[NN] = off + s_total;
}

// ---------------- CSR scatter: pack {src, dinv[src]} ------------------------
__global__ void k_scatter(const void* __restrict__ eidx) {
    int is64 = probe_is64((const int*)eidx);
    int i = blockIdx.x * blockDim.x + threadIdx.x;
    if (i * 2 >= EP) return;
    int r0, r1, c0, c1;
    if (is64) {
        const long long* e64 = (const long long*)eidx;
        longlong2 vr = ((const longlong2*)e64)[i];
        longlong2 vc = ((const longlong2*)(e64 + EP))[i];
        r0 = (int)vr.x; r1 = (int)vr.y;
        c0 = (int)vc.x; c1 = (int)vc.y;
    } else {
        const int* e32 = (const int*)eidx;
        int2 vr = ((const int2*)e32)[i];
        int2 vc = ((const int2*)(e32 + EP))[i];
        r0 = vr.x; r1 = vr.y;
        c0 = vc.x; c1 = vc.y;
    }
    float d0 = g_dinv[r0], d1 = g_dinv[r1];
    int p0 = atomicAdd(&g_cursor[c0], 1);
    g_edge[p0] = make_uint2((unsigned)r0, __float_as_uint(d0));
    int p1 = atomicAdd(&g_cursor[c1], 1);
    g_edge[p1] = make_uint2((unsigned)r1, __float_as_uint(d1));
}

// ---------------- GEMM1: 8 rows x 8 cols per thread, fp16 output -------------
__global__ __launch_bounds__(256) void k_gemm1(const float* __restrict__ x,
                                               const float* __restrict__ W) {
    __shared__ float Ws[FIN * FH];                // 32 KB
    int tx = threadIdx.x, ty = threadIdx.y;       // (8, 32)
    int tid = ty * 8 + tx;
    {
        const float4* W4 = (const float4*)W;
        float4* Ws4 = (float4*)Ws;
        for (int i = tid; i < FIN * FH / 4; i += 256) Ws4[i] = W4[i];
    }
    __syncthreads();
    int rbase = blockIdx.x * 256 + ty;            // rows: rbase + 32*i, i<8
    int cb = tx * 8;
    const float4* xp[8];
    bool vr[8];
    #pragma unroll
    for (int i = 0; i < 8; i++) {
        int r = rbase + i * 32;
        vr[i] = r < NN;
        xp[i] = (const float4*)(x + (size_t)(vr[i] ? r : 0) * FIN);
    }
    float acc[8][8];
    #pragma unroll
    for (int i = 0; i < 8; i++)
        #pragma unroll
        for (int j = 0; j < 8; j++) acc[i][j] = 0.f;
    for (int k4 = 0; k4 < FIN / 4; k4++) {
        float4 xv[8];
        #pragma unroll
        for (int i = 0; i < 8; i++) xv[i] = xp[i][k4];
        const float* w = &Ws[(k4 * 4) * FH + cb];
        #pragma unroll
        for (int kk = 0; kk < 4; kk++) {
            const float* wk = w + kk * FH;
            #pragma unroll
            for (int j = 0; j < 8; j++) {
                float wv = wk[j];
                #pragma unroll
                for (int i = 0; i < 8; i++)
                    acc[i][j] = fmaf(((const float*)&xv[i])[kk], wv, acc[i][j]);
            }
        }
    }
    #pragma unroll
    for (int i = 0; i < 8; i++) {
        if (vr[i]) {
            uint4 st;
            __half2 p0 = __floats2half2_rn(acc[i][0], acc[i][1]);
            __half2 p1 = __floats2half2_rn(acc[i][2], acc[i][3]);
            __half2 p2 = __floats2half2_rn(acc[i][4], acc[i][5]);
            __half2 p3 = __floats2half2_rn(acc[i][6], acc[i][7]);
            st.x = *(unsigned*)&p0; st.y = *(unsigned*)&p1;
            st.z = *(unsigned*)&p2; st.w = *(unsigned*)&p3;
            *(uint4*)(g_xw + (size_t)(rbase + i * 32) * FH + cb) = st;
        }
    }
}

// ---------------- agg1 fused with GEMM2: fp16 rows (128B), graduated ladder --
__global__ __launch_bounds__(256) void k_agg1f(const float* __restrict__ b1,
                                               const float* __restrict__ W2) {
    __shared__ float Ws[FH * FO];                 // 8 KB
    int tid = threadIdx.x;
    {
        const float4* W4 = (const float4*)W2;
        float4* Ws4 = (float4*)Ws;
        for (int i = tid; i < FH * FO / 4; i += 256) Ws4[i] = W4[i];
    }
    __syncthreads();
    int w = (blockIdx.x * 256 + tid) >> 5;
    if (w >= NN) return;
    int lane = tid & 31;
    int half_ = lane >> 4, q = lane & 15;         // q: 8B chunk of 128B row
    float dw = g_dinv[w];
    float4 acc = make_float4(0, 0, 0, 0);
    if (half_ == 0) {                             // self loop on half 0
        float4 sv = h4_to_f4(((const uint2*)(g_xw + (size_t)w * FH))[q]);
        acc.x = sv.x * dw; acc.y = sv.y * dw; acc.z = sv.z * dw; acc.w = sv.w * dw;
    }
    int s = g_rowptr[w], e = g_rowptr[w + 1];
    int p = s;
    for (; p + 16 <= e; p += 16) {
        uint2 r[8];
        #pragma unroll
        for (int t = 0; t < 8; t++) r[t] = g_edge[p + 2 * t + half_];
        uint2 u[8];
        #pragma unroll
        for (int t = 0; t < 8; t++)
            u[t] = ((const uint2*)(g_xw + (size_t)r[t].x * FH))[q];
        #pragma unroll
        for (int t = 0; t < 8; t++) {
            float d = __uint_as_float(r[t].y);
            float4 f = h4_to_f4(u[t]);
            acc.x = fmaf(f.x, d, acc.x); acc.y = fmaf(f.y, d, acc.y);
            acc.z = fmaf(f.z, d, acc.z); acc.w = fmaf(f.w, d, acc.w);
        }
    }
    for (; p + 8 <= e; p += 8) {
        uint2 r[4];
        #pragma unroll
        for (int t = 0; t < 4; t++) r[t] = g_edge[p + 2 * t + half_];
        uint2 u[4];
        #pragma unroll
        for (int t = 0; t < 4; t++)
            u[t] = ((const uint2*)(g_xw + (size_t)r[t].x * FH))[q];
        #pragma unroll
        for (int t = 0; t < 4; t++) {
            float d = __uint_as_float(r[t].y);
            float4 f = h4_to_f4(u[t]);
            acc.x = fmaf(f.x, d, acc.x); acc.y = fmaf(f.y, d, acc.y);
            acc.z = fmaf(f.z, d, acc.z); acc.w = fmaf(f.w, d, acc.w);
        }
    }
    for (; p + 2 <= e; p += 2) {
        uint2 r0 = g_edge[p + half_];
        float4 f = h4_to_f4(((const uint2*)(g_xw + (size_t)r0.x * FH))[q]);
        float d0 = __uint_as_float(r0.y);
        acc.x = fmaf(f.x, d0, acc.x); acc.y = fmaf(f.y, d0, acc.y);
        acc.z = fmaf(f.z, d0, acc.z); acc.w = fmaf(f.w, d0, acc.w);
    }
    if (p < e) {                                  // odd edge: half 0 only
        uint2 r0 = g_edge[p];
        float4 f = h4_to_f4(((const uint2*)(g_xw + (size_t)r0.x * FH))[q]);
        float d0 = half_ ? 0.f : __uint_as_float(r0.y);
        acc.x = fmaf(f.x, d0, acc.x); acc.y = fmaf(f.y, d0, acc.y);
        acc.z = fmaf(f.z, d0, acc.z); acc.w = fmaf(f.w, d0, acc.w);
    }
    acc.x += __shfl_xor_sync(0xffffffffu, acc.x, 16);
    acc.y += __shfl_xor_sync(0xffffffffu, acc.y, 16);
    acc.z += __shfl_xor_sync(0xffffffffu, acc.z, 16);
    acc.w += __shfl_xor_sync(0xffffffffu, acc.w, 16);
    float4 bias = ((const float4*)b1)[q];
    float4 h;
    h.x = fmaxf(fmaf(acc.x, dw, bias.x), 0.f);
    h.y = fmaxf(fmaf(acc.y, dw, bias.y), 0.f);
    h.z = fmaxf(fmaf(acc.z, dw, bias.z), 0.f);
    h.w = fmaxf(fmaf(acc.w, dw, bias.w), 0.f);
    float o = 0.f;
    #pragma unroll
    for (int f4 = 0; f4 < 16; f4++) {
        float h0 = __shfl_sync(0xffffffffu, h.x, f4);
        float h1 = __shfl_sync(0xffffffffu, h.y, f4);
        float h2 = __shfl_sync(0xffffffffu, h.z, f4);
        float h3 = __shfl_sync(0xffffffffu, h.w, f4);
        o = fmaf(h0, Ws[(f4 * 4 + 0) * FO + lane], o);
        o = fmaf(h1, Ws[(f4 * 4 + 1) * FO + lane], o);
        o = fmaf(h2, Ws[(f4 * 4 + 2) * FO + lane], o);
        o = fmaf(h3, Ws[(f4 * 4 + 3) * FO + lane], o);
    }
    g_hw[(size_t)w * FO + lane] = __float2half_rn(o);
}

// ---------------- agg2: fp16 rows (64B), graduated ladder; z fp16 ------------
__global__ __launch_bounds__(256) void k_agg2(const float* __restrict__ b) {
    int w = (blockIdx.x * 256 + threadIdx.x) >> 5;
    if (w >= NN) return;
    int lane = threadIdx.x & 31;
    int g = lane >> 3, l8 = lane & 7;             // l8: 8B chunk of 64B row
    float dw = g_dinv[w];
    float4 acc = make_float4(0, 0, 0, 0);
    if (g == 0) {
        float4 sv = h4_to_f4(((const uint2*)(g_hw + (size_t)w * FO))[l8]);
        acc.x = sv.x * dw; acc.y = sv.y * dw; acc.z = sv.z * dw; acc.w = sv.w * dw;
    }
    int s = g_rowptr[w], e = g_rowptr[w + 1];
    int p = s;
    for (; p + 8 <= e; p += 8) {
        uint2 r0 = g_edge[p     + g];
        uint2 r1 = g_edge[p + 4 + g];
        float4 u0 = h4_to_f4(((const uint2*)(g_hw + (size_t)r0.x * FO))[l8]);
        float4 u1 = h4_to_f4(((const uint2*)(g_hw + (size_t)r1.x * FO))[l8]);
        float d0 = __uint_as_float(r0.y), d1 = __uint_as_float(r1.y);
        acc.x = fmaf(u0.x, d0, acc.x); acc.y = fmaf(u0.y, d0, acc.y);
        acc.z = fmaf(u0.z, d0, acc.z); acc.w = fmaf(u0.w, d0, acc.w);
        acc.x = fmaf(u1.x, d1, acc.x); acc.y = fmaf(u1.y, d1, acc.y);
        acc.z = fmaf(u1.z, d1, acc.z); acc.w = fmaf(u1.w, d1, acc.w);
    }
    for (; p + 4 <= e; p += 4) {
        uint2 r0 = g_edge[p + g];
        float4 u0 = h4_to_f4(((const uint2*)(g_hw + (size_t)r0.x * FO))[l8]);
        float d0 = __uint_as_float(r0.y);
        acc.x = fmaf(u0.x, d0, acc.x); acc.y = fmaf(u0.y, d0, acc.y);
        acc.z = fmaf(u0.z, d0, acc.z); acc.w = fmaf(u0.w, d0, acc.w);
    }
    if (p < e) {
        int rem = e - p;
        uint2 r0 = g_edge[p + (g < rem ? g : 0)];
        float4 u0 = h4_to_f4(((const uint2*)(g_hw + (size_t)r0.x * FO))[l8]);
        float d0 = (g < rem) ? __uint_as_float(r0.y) : 0.f;
        acc.x = fmaf(u0.x, d0, acc.x); acc.y = fmaf(u0.y, d0, acc.y);
        acc.z = fmaf(u0.z, d0, acc.z); acc.w = fmaf(u0.w, d0, acc.w);
    }
    #pragma unroll
    for (int o = 8; o <= 16; o <<= 1) {
        acc.x += __shfl_xor_sync(0xffffffffu, acc.x, o);
        acc.y += __shfl_xor_sync(0xffffffffu, acc.y, o);
        acc.z += __shfl_xor_sync(0xffffffffu, acc.z, o);
        acc.w += __shfl_xor_sync(0xffffffffu, acc.w, o);
    }
    if (g == 0) {
        float4 bias = ((const float4*)b)[l8];
        __half2 z0 = __floats2half2_rn(fmaf(acc.x, dw, bias.x),
                                       fmaf(acc.y, dw, bias.y));
        __half2 z1 = __floats2half2_rn(fmaf(acc.z, dw, bias.z),
                                       fmaf(acc.w, dw, bias.w));
        uint2 st;
        st.x = *(unsigned*)&z0;
        st.y = *(unsigned*)&z1;
        ((uint2*)(g_z + (size_t)w * FO))[l8] = st;   // 8B per lane, 64B row
    }
}

// ---------------- decode: 32 edges/warp, fp16 z gathers ----------------------
__global__ __launch_bounds__(256) void k_decode(const void* __restrict__ pos,
                                                const void* __restrict__ neg,
                                                float* __restrict__ out) {
    int is64 = probe_is64((const int*)pos);
    int warp = (blockIdx.x * 256 + threadIdx.x) >> 5;
    int lane = threadIdx.x & 31;
    int sub = lane >> 3, l8 = lane & 7;
    size_t base = (size_t)warp * 32 + sub * 8;      // EP%8==0: one-sided
    const void* buf; size_t off;
    if (base < EP) { buf = pos; off = base; }
    else           { buf = neg; off = base - EP; }
    int a[8], c[8];
    if (!is64) {
        const int* e32 = (const int*)buf;
        int4 a0 = *(const int4*)(e32 + off);
        int4 a1 = *(const int4*)(e32 + off + 4);
        int4 c0 = *(const int4*)(e32 + EP + off);
        int4 c1 = *(const int4*)(e32 + EP + off + 4);
        a[0] = a0.x; a[1] = a0.y; a[2] = a0.z; a[3] = a0.w;
        a[4] = a1.x; a[5] = a1.y; a[6] = a1.z; a[7] = a1.w;
        c[0] = c0.x; c[1] = c0.y; c[2] = c0.z; c[3] = c0.w;
        c[4] = c1.x; c[5] = c1.y; c[6] = c1.z; c[7] = c1.w;
    } else {
        const long long* e64 = (const long long*)buf;
        #pragma unroll
        for (int t = 0; t < 4; t++) {
            longlong2 pa = *(const longlong2*)(e64 + off + 2 * t);
            longlong2 pc = *(const longlong2*)(e64 + EP + off + 2 * t);
            a[2 * t] = (int)pa.x; a[2 * t + 1] = (int)pa.y;
            c[2 * t] = (int)pc.x; c[2 * t + 1] = (int)pc.y;
        }
    }
    uint2 ua[8], ub[8];
    #pragma unroll
    for (int t = 0; t < 8; t++) {
        ua[t] = ((const uint2*)(g_z + (size_t)a[t] * FO))[l8];
        ub[t] = ((const uint2*)(g_z + (size_t)c[t] * FO))[l8];
    }
    float v[8];
    #pragma unroll
    for (int t = 0; t < 8; t++) {
        float4 fa = h4_to_f4(ua[t]);
        float4 fb = h4_to_f4(ub[t]);
        v[t] = fa.x * fb.x + fa.y * fb.y + fa.z * fb.z + fa.w * fb.w;
    }
    #pragma unroll
    for (int o = 4; o; o >>= 1) {
        #pragma unroll
        for (int t = 0; t < 8; t++) v[t] += __shfl_xor_sync(0xffffffffu, v[t], o);
    }
    if (l8 == 0) {
        ((float4*)out)[(base >> 2)]     = make_float4(v[0], v[1], v[2], v[3]);
        ((float4*)out)[(base >> 2) + 1] = make_float4(v[4], v[5], v[6], v[7]);
    }
}

// edge_index echoed as floats (2 elems / thread) ------------------------------
__global__ void k_tail(const void* __restrict__ pos,
                       const void* __restrict__ neg,
                       float* __restrict__ out, int count) {
    int is64 = probe_is64((const int*)pos);
    int i = (blockIdx.x * blockDim.x + threadIdx.x) * 2;
    if (i >= count) return;
    int r = i / ET, c = i % ET;                    // ET%2==0: pair same row
    int v0, v1;
    const void* buf = (c < EP) ? pos : neg;
    size_t off = (size_t)r * EP + ((c < EP) ? c : c - EP);
    if (c + 1 == EP || c + 1 == ET) {              // straddle: scalar
        v0 = edge_at(buf, is64, off);
        v1 = (c + 1 < ET) ? edge_at(neg, is64, (size_t)r * EP) :
             ((r == 0) ? edge_at(pos, is64, EP) : 0);
        out[ET + i] = (float)v0;
        if (i + 1 < count) out[ET + i + 1] = (float)v1;
        return;
    }
    if (is64) {
        longlong2 p2 = ((const longlong2*)((const long long*)buf))[off / 2];
        v0 = (int)p2.x; v1 = (int)p2.y;
    } else {
        int2 p2 = ((const int2*)((const int*)buf))[off / 2];
        v0 = p2.x; v1 = p2.y;
    }
    ((float2*)(out + ET))[i / 2] = make_float2((float)v0, (float)v1);
}

// ---------------- launcher ---------------------------------------------------
extern "C" void kernel_launch(void* const* d_in, const int* in_sizes, int n_in,
                              void* d_out, int out_size) {
    static cudaStream_t s2 = 0;
    static cudaEvent_t evFork = 0, evJoin = 0, evTail = 0;
    if (!s2) {
        cudaStreamCreateWithFlags(&s2, cudaStreamNonBlocking);
        cudaEventCreateWithFlags(&evFork, cudaEventDisableTiming);
        cudaEventCreateWithFlags(&evJoin, cudaEventDisableTiming);
        cudaEventCreateWithFlags(&evTail, cudaEventDisableTiming);
    }

    const float *x = 0, *W1 = 0, *b1 = 0, *W2 = 0, *b2 = 0;
    const void *pos = 0, *neg = 0;
    for (int i = 0; i < n_in; i++) {
        switch (in_sizes[i]) {
            case NN * FIN:  x  = (const float*)d_in[i]; break;
            case FIN * FH:  W1 = (const float*)d_in[i]; break;
            case FH:        b1 = (const float*)d_in[i]; break;
            case FH * FO:   W2 = (const float*)d_in[i]; break;
            case FO:        b2 = (const float*)d_in[i]; break;
            case 2 * EP:
                if (!pos) pos = d_in[i];
                else      neg = d_in[i];
                break;
            default: break;
        }
    }
    float* out = (float*)d_out;

    // fork: GEMM1 + edge echo (independent of graph preprocessing) on s2
    cudaEventRecord(evFork, 0);
    cudaStreamWaitEvent(s2, evFork, 0);
    k_gemm1<<<(NN + 255) / 256, dim3(8, 32), 0, s2>>>(x, W1);
    cudaEventRecord(evJoin, s2);
    int cnt = 0;
    if (out_size > ET) {
        cnt = out_size - ET;
        if (cnt > 2 * ET) cnt = 2 * ET;
        k_tail<<<((cnt + 1) / 2 + 255) / 256, 256, 0, s2>>>(pos, neg, out, cnt);
        cudaEventRecord(evTail, s2);
    }

    // preprocessing chain on main stream (deg pre-zeroed: self-cleaning)
    k_hist   <<<(EP / 2 + 255) / 256, 256>>>(pos);
    k_scanA  <<<NB, 256>>>();
    k_scanC  <<<NB, 256>>>();
    k_scatter<<<(EP / 2 + 255) / 256, 256>>>(pos);

    // join gemm1, then fused layer pipeline (flat grids)
    cudaStreamWaitEvent(0, evJoin, 0);
    k_agg1f<<<(NN * 32 + 255) / 256, 256>>>(b1, W2);
    k_agg2 <<<(NN * 32 + 255) / 256, 256>>>(b2);

    // decode writes out[0..ET), tail writes out[ET..): disjoint — join after
    k_decode<<<(ET / 32) * 32 / 256, 256>>>(pos, neg, out);
    if (cnt) cudaStreamWaitEvent(0, evTail, 0);
}